// round 15
// baseline (speedup 1.0000x reference)
#include <cuda_runtime.h>
#include <cuda_bf16.h>
#include <math.h>
#include <stdint.h>

#define TT 2048
#define HH 1024
#define DD 512
#define EE 64
#define TOPK 2
#define NTILES 128   // BM=64: sum ceil(cnt_e/64) <= 127

// smem row stride in 32-bit words (80 B rows; 16B-aligned, conflict-free ldmatrix)
#define RS 20
#define RSB (RS * 4)
#define STG_U32 7680
#define STG_B   30720
#define SMEM_DYN (2 * STG_B)

// ---------------- scratch ----------------
__device__ int   g_topk_i[TT * TOPK];
__device__ float g_topk_w[TT * TOPK];
__device__ int   g_counts[EE];
__device__ int   g_list[EE * TT];
__device__ float g_usage_partial[64 * EE];
__device__ int2  g_tiles[NTILES];
__device__ __nv_bfloat16 g_xh[TT * HH], g_xl[TT * HH];
__device__ __nv_bfloat16 g_ah[TT * TOPK * DD], g_al[TT * TOPK * DD];

// ---------------- helpers ----------------
__device__ __forceinline__ uint32_t pack_bf2(__nv_bfloat16 a, __nv_bfloat16 b) {
    return (uint32_t)__bfloat16_as_ushort(a) | ((uint32_t)__bfloat16_as_ushort(b) << 16);
}
__device__ __forceinline__ void split32(float v, __nv_bfloat16& h, __nv_bfloat16& l) {
    h = __float2bfloat16(v);
    l = __float2bfloat16(v - __bfloat162float(h));
}
__device__ __forceinline__ void split_pack(float a, float b, uint32_t& hi, uint32_t& lo) {
    __nv_bfloat16 h0, h1, l0, l1;
    split32(a, h0, l0); split32(b, h1, l1);
    hi = pack_bf2(h0, h1); lo = pack_bf2(l0, l1);
}
__device__ __forceinline__ void mma16816(float* d, const uint32_t* a, const uint32_t* b) {
    asm volatile("mma.sync.aligned.m16n8k16.row.col.f32.bf16.bf16.f32 "
        "{%0,%1,%2,%3}, {%4,%5,%6,%7}, {%8,%9}, {%0,%1,%2,%3};"
        : "+f"(d[0]), "+f"(d[1]), "+f"(d[2]), "+f"(d[3])
        : "r"(a[0]), "r"(a[1]), "r"(a[2]), "r"(a[3]), "r"(b[0]), "r"(b[1]));
}
__device__ __forceinline__ uint32_t smaddr(const void* p) {
    return (uint32_t)__cvta_generic_to_shared(p);
}
__device__ __forceinline__ void ldm_x4(uint32_t* r, uint32_t a) {
    asm volatile("ldmatrix.sync.aligned.m8n8.x4.shared.b16 {%0,%1,%2,%3}, [%4];"
                 : "=r"(r[0]), "=r"(r[1]), "=r"(r[2]), "=r"(r[3]) : "r"(a));
}

// ---------------- router (+ out-zeroing + x-split; NO atomics) ----------------
__global__ __launch_bounds__(256) void k_router(const float* __restrict__ x,
                                                const float* __restrict__ gate,
                                                float* __restrict__ out) {
    __shared__ float Xs[32][33];
    __shared__ float Gs[32][68];
    __shared__ float Ls[32][65];
    __shared__ float sM[32], sInv[32];

    const int t0 = blockIdx.x * 32;
    const int tid = threadIdx.x;
    const int tx = tid & 15, ty = tid >> 4;

    // zero this block's slice of out (independent work)
    {
        float4* ob = ((float4*)out) + (size_t)blockIdx.x * 8192;
        float4 z = make_float4(0.f, 0.f, 0.f, 0.f);
#pragma unroll
        for (int i = 0; i < 32; i++) ob[tid + i * 256] = z;
    }

    float acc[2][4];
#pragma unroll
    for (int i = 0; i < 2; i++)
#pragma unroll
        for (int j = 0; j < 4; j++) acc[i][j] = 0.f;

    for (int k0 = 0; k0 < HH; k0 += 32) {
        {
            int m = tid >> 3, k4 = (tid & 7) * 4;
            float4 v = *(const float4*)(x + (size_t)(t0 + m) * HH + k0 + k4);
            Xs[m][k4 + 0] = v.x; Xs[m][k4 + 1] = v.y;
            Xs[m][k4 + 2] = v.z; Xs[m][k4 + 3] = v.w;
            // fused split of x into bf16 hi/lo
            uint2 ph, pl;
            split_pack(v.x, v.y, ph.x, pl.x);
            split_pack(v.z, v.w, ph.y, pl.y);
            size_t off = (size_t)(t0 + m) * HH + k0 + k4;
            *(uint2*)(g_xh + off) = ph;
            *(uint2*)(g_xl + off) = pl;
        }
        {
            int k = tid >> 4, j4 = (tid & 15) * 4;
#pragma unroll
            for (int r = 0; r < 2; r++) {
                float4 v = *(const float4*)(gate + (size_t)(k0 + k + r * 16) * EE + j4);
                *(float4*)&Gs[k + r * 16][j4] = v;
            }
        }
        __syncthreads();
#pragma unroll
        for (int kk = 0; kk < 32; kk++) {
            float a0 = Xs[ty * 2 + 0][kk];
            float a1 = Xs[ty * 2 + 1][kk];
            float4 b = *(float4*)&Gs[kk][tx * 4];
            acc[0][0] += a0 * b.x; acc[0][1] += a0 * b.y; acc[0][2] += a0 * b.z; acc[0][3] += a0 * b.w;
            acc[1][0] += a1 * b.x; acc[1][1] += a1 * b.y; acc[1][2] += a1 * b.z; acc[1][3] += a1 * b.w;
        }
        __syncthreads();
    }
#pragma unroll
    for (int mi = 0; mi < 2; mi++)
#pragma unroll
        for (int ni = 0; ni < 4; ni++)
            Ls[ty * 2 + mi][tx * 4 + ni] = acc[mi][ni];
    __syncthreads();

    if (tid < 32) {
        int t = t0 + tid;
        float m1 = -1e30f, m2 = -1e30f;
        int i1 = -1, i2 = -1;
        for (int e = 0; e < EE; e++) {
            float l = Ls[tid][e];
            if (l > m1) { m2 = m1; i2 = i1; m1 = l; i1 = e; }
            else if (l > m2) { m2 = l; i2 = e; }
        }
        float den = 0.f;
        for (int e = 0; e < EE; e++) den += __expf(Ls[tid][e] - m1);
        sM[tid] = m1; sInv[tid] = 1.f / den;
        float e2 = __expf(m2 - m1);
        float s = 1.f + e2;
        g_topk_i[t * 2 + 0] = i1;
        g_topk_i[t * 2 + 1] = i2;
        g_topk_w[t * 2 + 0] = 1.f / s;
        g_topk_w[t * 2 + 1] = e2 / s;
    }
    __syncthreads();

    if (tid < EE) {
        float s = 0.f;
        for (int r = 0; r < 32; r++)
            s += __expf(Ls[r][tid] - sM[r]) * sInv[r];
        g_usage_partial[blockIdx.x * EE + tid] = s;
    }
}

// ---------------- histogram list-build + tiles (BM=64) + lb; 1 block, 256 thr ----------------
__global__ void k_build_tiles2(float* __restrict__ out_lb) {
    __shared__ int sCnt[EE];
    __shared__ int sBase[EE];
    __shared__ int sPos[EE];
    __shared__ float red[64];

    const int tid = threadIdx.x;
    if (tid < EE) { sCnt[tid] = 0; sPos[tid] = 0; }
    for (int i = tid; i < NTILES; i += 256) g_tiles[i] = make_int2(-1, 0);
    __syncthreads();

    // histogram
    for (int i = tid; i < TT * TOPK; i += 256)
        atomicAdd(&sCnt[g_topk_i[i]], 1);
    __syncthreads();

    if (tid == 0) {
        int a = 0;
        for (int e = 0; e < EE; e++) { sBase[e] = a; a += (sCnt[e] + 63) >> 6; }
    }
    __syncthreads();

    // scatter into per-expert lists (order within expert irrelevant; sums commute)
    for (int i = tid; i < TT * TOPK; i += 256) {
        int e = g_topk_i[i];
        int pos = atomicAdd(&sPos[e], 1);
        g_list[e * TT + pos] = i;
    }

    // counts + tiles + lb
    if (tid < EE) {
        int e = tid;
        g_counts[e] = sCnt[e];
        int nt = (sCnt[e] + 63) >> 6;
        int base = sBase[e];
        for (int i = 0; i < nt; i++) g_tiles[base + i] = make_int2(e, i * 64);
        float s = 0.f;
        for (int b = 0; b < 64; b++) s += g_usage_partial[b * EE + e];
        float u = s / (float)TT;
        red[e] = u * u;
    }
    __syncthreads();
    if (tid < 64) {
        for (int off = 32; off > 0; off >>= 1) {
            if (tid < off) red[tid] += red[tid + off];
            __syncwarp(0xFFFFFFFF);
        }
        if (tid == 0 && out_lb) *out_lb = (float)EE * red[0];
    }
}

// ================= GEMM A: BM=64, BN=64, BK=32; double-buffered; reg-staged =================
__global__ __launch_bounds__(256, 2) void k_gemmA(const float* __restrict__ w1,
                                                  const float* __restrict__ w3) {
    extern __shared__ uint32_t smp[];
    __shared__ int sPair[64];
    uint32_t* XSh = smp;
    uint32_t* XSl = smp + 1280;
    uint32_t* W1h = smp + 2560;
    uint32_t* W1l = smp + 3840;
    uint32_t* W3h = smp + 5120;
    uint32_t* W3l = smp + 6400;

    int2 tile = g_tiles[blockIdx.x];
    if (tile.x < 0) return;
    const int e = tile.x, t0 = tile.y;
    const int d0 = blockIdx.y * 64;
    const int tid = threadIdx.x;
    const int lane = tid & 31, wid = tid >> 5;
    const int g = lane >> 2, q = lane & 3;
    const int warp_m = wid & 1, warp_n = wid >> 1;
    const int cnt = g_counts[e];

    if (tid < 64) {
        int idx = t0 + tid;
        sPair[tid] = (idx < cnt) ? g_list[e * TT + idx] : -1;
    }
    __syncthreads();

    const float* w1e = w1 + (size_t)e * HH * DD;
    const float* w3e = w3 + (size_t)e * HH * DD;

    const int xrow = tid >> 2, xkp = (tid & 3) * 4;
    const int xp = sPair[xrow];
    const __nv_bfloat16* xsh = (xp >= 0) ? (g_xh + (size_t)(xp >> 1) * HH + xkp * 2) : 0;
    const __nv_bfloat16* xsl = (xp >= 0) ? (g_xl + (size_t)(xp >> 1) * HH + xkp * 2) : 0;
    const int dd = tid & 63, q4 = tid >> 6;
    const float* w1p = w1e + (size_t)(q4 * 8) * DD + d0 + dd;
    const float* w3p = w3e + (size_t)(q4 * 8) * DD + d0 + dd;

    const int arow = warp_m * 32 + (lane & 15);
    const int acof = (lane >> 4) * 4;
    const uint32_t aXh = smaddr(&XSh[arow * RS + acof]);
    const uint32_t aXl = smaddr(&XSl[arow * RS + acof]);
    const int nrow = warp_n * 16 + (lane >> 4) * 8 + (lane & 7);
    const int ncof = ((lane >> 3) & 1) * 4;
    const uint32_t aW1h = smaddr(&W1h[nrow * RS + ncof]);
    const uint32_t aW1l = smaddr(&W1l[nrow * RS + ncof]);
    const uint32_t aW3h = smaddr(&W3h[nrow * RS + ncof]);
    const uint32_t aW3l = smaddr(&W3l[nrow * RS + ncof]);

    float acc1[2][2][4], acc3[2][2][4];
#pragma unroll
    for (int a = 0; a < 2; a++)
#pragma unroll
        for (int b = 0; b < 2; b++)
#pragma unroll
            for (int c = 0; c < 4; c++) { acc1[a][b][c] = 0.f; acc3[a][b][c] = 0.f; }

    uint4 pvh, pvl;
    float pw1[8], pw3[8];
#define GA_LOAD(K0)                                                        \
    {                                                                      \
        pvh = make_uint4(0, 0, 0, 0); pvl = make_uint4(0, 0, 0, 0);        \
        if (xp >= 0) {                                                     \
            pvh = *(const uint4*)(xsh + (K0));                             \
            pvl = *(const uint4*)(xsl + (K0));                             \
        }                                                                  \
        const float* p1 = w1p + (size_t)(K0) * DD;                         \
        const float* p3 = w3p + (size_t)(K0) * DD;                         \
        _Pragma("unroll")                                                  \
        for (int i = 0; i < 8; i++) { pw1[i] = p1[i * DD]; pw3[i] = p3[i * DD]; } \
    }

    GA_LOAD(0)
    const int NC = HH / 32;
    for (int c = 0; c < NC; c++) {
        const int bo = (c & 1) * STG_U32;
        const uint32_t bob = (uint32_t)(c & 1) * STG_B;
        // stage X and weights for chunk c (STS.128)
        *(uint4*)&XSh[bo + xrow * RS + xkp] = pvh;
        *(uint4*)&XSl[bo + xrow * RS + xkp] = pvl;
        {
            uint32_t h[4], l[4];
            split_pack(pw1[0], pw1[1], h[0], l[0]);
            split_pack(pw1[2], pw1[3], h[1], l[1]);
            split_pack(pw1[4], pw1[5], h[2], l[2]);
            split_pack(pw1[6], pw1[7], h[3], l[3]);
            *(uint4*)&W1h[bo + dd * RS + q4 * 4] = make_uint4(h[0], h[1], h[2], h[3]);
            *(uint4*)&W1l[bo + dd * RS + q4 * 4] = make_uint4(l[0], l[1], l[2], l[3]);
            split_pack(pw3[0], pw3[1], h[0], l[0]);
            split_pack(pw3[2], pw3[3], h[1], l[1]);
            split_pack(pw3[4], pw3[5], h[2], l[2]);
            split_pack(pw3[6], pw3[7], h[3], l[3]);
            *(uint4*)&W3h[bo + dd * RS + q4 * 4] = make_uint4(h[0], h[1], h[2], h[3]);
            *(uint4*)&W3l[bo + dd * RS + q4 * 4] = make_uint4(l[0], l[1], l[2], l[3]);
        }
        // issue next chunk's global loads BEFORE the barrier (head start)
        if (c + 1 < NC) GA_LOAD((c + 1) * 32)
        __syncthreads();

#pragma unroll
        for (int s = 0; s < 2; s++) {
            const uint32_t s32 = bob + s * 32;
            uint32_t ah[2][4], al[2][4];
            ldm_x4(ah[0], aXh + s32);
            ldm_x4(ah[1], aXh + 16 * RSB + s32);
            ldm_x4(al[0], aXl + s32);
            ldm_x4(al[1], aXl + 16 * RSB + s32);
            uint32_t b1h[4], b1l[4], b3h[4], b3l[4];
            ldm_x4(b1h, aW1h + s32);
            ldm_x4(b1l, aW1l + s32);
            ldm_x4(b3h, aW3h + s32);
            ldm_x4(b3l, aW3l + s32);
#pragma unroll
            for (int nf = 0; nf < 2; nf++) {
#pragma unroll
                for (int mf = 0; mf < 2; mf++) {
                    mma16816(acc1[mf][nf], ah[mf], b1h + nf * 2);
                    mma16816(acc1[mf][nf], ah[mf], b1l + nf * 2);
                    mma16816(acc1[mf][nf], al[mf], b1h + nf * 2);
                    mma16816(acc3[mf][nf], ah[mf], b3h + nf * 2);
                    mma16816(acc3[mf][nf], ah[mf], b3l + nf * 2);
                    mma16816(acc3[mf][nf], al[mf], b3h + nf * 2);
                }
            }
        }
    }

#pragma unroll
    for (int mf = 0; mf < 2; mf++) {
        int rbase = warp_m * 32 + mf * 16 + g;
#pragma unroll
        for (int half = 0; half < 2; half++) {
            int r = rbase + half * 8;
            int p = sPair[r];
            if (p < 0) continue;
#pragma unroll
            for (int nf = 0; nf < 2; nf++) {
                int dcol = d0 + warp_n * 16 + nf * 8 + q * 2;
                float h0 = acc1[mf][nf][half * 2 + 0], g0 = acc3[mf][nf][half * 2 + 0];
                float h1 = acc1[mf][nf][half * 2 + 1], g1 = acc3[mf][nf][half * 2 + 1];
                float o0 = h0 * g0 / (1.f + __expf(-h0));
                float o1 = h1 * g1 / (1.f + __expf(-h1));
                uint32_t hi, lo;
                split_pack(o0, o1, hi, lo);
                *(uint32_t*)(g_ah + (size_t)p * DD + dcol) = hi;
                *(uint32_t*)(g_al + (size_t)p * DD + dcol) = lo;
            }
        }
    }
}

// ================= GEMM B: BM=64, BN=128, BK=32; double-buffered; reg-staged =================
__global__ __launch_bounds__(256, 2) void k_gemmB(const float* __restrict__ w2,
                                                  float* __restrict__ out) {
    extern __shared__ uint32_t smp[];
    __shared__ int sPair[64];
    __shared__ float sW[64];
    uint32_t* ASh = smp;
    uint32_t* ASl = smp + 1280;
    uint32_t* W2h = smp + 2560;
    uint32_t* W2l = smp + 5120;

    int2 tile = g_tiles[blockIdx.x];
    if (tile.x < 0) return;
    const int e = tile.x, t0 = tile.y;
    const int h0 = blockIdx.y * 128;
    const int tid = threadIdx.x;
    const int lane = tid & 31, wid = tid >> 5;
    const int g = lane >> 2, q = lane & 3;
    const int warp_m = wid & 1, warp_n = wid >> 1;
    const int cnt = g_counts[e];

    if (tid < 64) {
        int idx = t0 + tid;
        int p = (idx < cnt) ? g_list[e * TT + idx] : -1;
        sPair[tid] = p;
        sW[tid] = (p >= 0) ? g_topk_w[p] : 0.f;
    }
    __syncthreads();

    const float* w2e = w2 + (size_t)e * DD * HH;

    const int xrow = tid >> 2, xkp = (tid & 3) * 4;
    const int xp = sPair[xrow];
    const __nv_bfloat16* ash = (xp >= 0) ? (g_ah + (size_t)xp * DD + xkp * 2) : 0;
    const __nv_bfloat16* asl = (xp >= 0) ? (g_al + (size_t)xp * DD + xkp * 2) : 0;
    const int hh = tid & 127, qh = tid >> 7;
    const float* w2p = w2e + (size_t)(qh * 16) * HH + h0 + hh;

    const int arow = warp_m * 32 + (lane & 15);
    const int acof = (lane >> 4) * 4;
    const uint32_t aAh = smaddr(&ASh[arow * RS + acof]);
    const uint32_t aAl = smaddr(&ASl[arow * RS + acof]);
    const int nrow = warp_n * 32 + (lane >> 4) * 8 + (lane & 7);
    const int ncof = ((lane >> 3) & 1) * 4;
    const uint32_t aW2h = smaddr(&W2h[nrow * RS + ncof]);
    const uint32_t aW2l = smaddr(&W2l[nrow * RS + ncof]);

    float acc[2][4][4];
#pragma unroll
    for (int a = 0; a < 2; a++)
#pragma unroll
        for (int b = 0; b < 4; b++)
#pragma unroll
            for (int c = 0; c < 4; c++) acc[a][b][c] = 0.f;

    uint4 pvh, pvl;
    float pw2[16];
#define GB_LOAD(K0)                                                        \
    {                                                                      \
        pvh = make_uint4(0, 0, 0, 0); pvl = make_uint4(0, 0, 0, 0);        \
        if (xp >= 0) {                                                     \
            pvh = *(const uint4*)(ash + (K0));                             \
            pvl = *(const uint4*)(asl + (K0));                             \
        }                                                                  \
        const float* p2 = w2p + (size_t)(K0) * HH;                         \
        _Pragma("unroll")                                                  \
        for (int i = 0; i < 16; i++) pw2[i] = p2[i * HH];                  \
    }

    GB_LOAD(0)
    const int NC = DD / 32;
    for (int c = 0; c < NC; c++) {
        const int bo = (c & 1) * STG_U32;
        const uint32_t bob = (uint32_t)(c & 1) * STG_B;
        *(uint4*)&ASh[bo + xrow * RS + xkp] = pvh;
        *(uint4*)&ASl[bo + xrow * RS + xkp] = pvl;
        {
            uint32_t h[8], l[8];
#pragma unroll
            for (int j = 0; j < 8; j++) split_pack(pw2[2 * j], pw2[2 * j + 1], h[j], l[j]);
            *(uint4*)&W2h[bo + hh * RS + qh * 8 + 0] = make_uint4(h[0], h[1], h[2], h[3]);
            *(uint4*)&W2h[bo + hh * RS + qh * 8 + 4] = make_uint4(h[4], h[5], h[6], h[7]);
            *(uint4*)&W2l[bo + hh * RS + qh * 8 + 0] = make_uint4(l[0], l[1], l[2], l[3]);
            *(uint4*)&W2l[bo + hh * RS + qh * 8 + 4] = make_uint4(l[4], l[5], l[6], l[7]);
        }
        if (c + 1 < NC) GB_LOAD((c + 1) * 32)
        __syncthreads();

#pragma unroll
        for (int s = 0; s < 2; s++) {
            const uint32_t s32 = bob + s * 32;
            uint32_t ah[2][4], al[2][4];
            ldm_x4(ah[0], aAh + s32);
            ldm_x4(ah[1], aAh + 16 * RSB + s32);
            ldm_x4(al[0], aAl + s32);
            ldm_x4(al[1], aAl + 16 * RSB + s32);
#pragma unroll
            for (int np = 0; np < 2; np++) {
                uint32_t bh[4], bl[4];
                ldm_x4(bh, aW2h + np * 16 * RSB + s32);
                ldm_x4(bl, aW2l + np * 16 * RSB + s32);
#pragma unroll
                for (int sub = 0; sub < 2; sub++) {
                    int nf = np * 2 + sub;
#pragma unroll
                    for (int mf = 0; mf < 2; mf++) {
                        mma16816(acc[mf][nf], ah[mf], bh + sub * 2);
                        mma16816(acc[mf][nf], ah[mf], bl + sub * 2);
                        mma16816(acc[mf][nf], al[mf], bh + sub * 2);
                    }
                }
            }
        }
    }

#pragma unroll
    for (int mf = 0; mf < 2; mf++) {
        int rbase = warp_m * 32 + mf * 16 + g;
#pragma unroll
        for (int half = 0; half < 2; half++) {
            int r = rbase + half * 8;
            int p = sPair[r];
            if (p < 0) continue;
            int tok = p >> 1;
            float wgt = sW[r];
            float* orow = out + (size_t)tok * HH;
#pragma unroll
            for (int nf = 0; nf < 4; nf++) {
                int hcol = h0 + warp_n * 32 + nf * 8 + q * 2;
                atomicAdd(orow + hcol + 0, acc[mf][nf][half * 2 + 0] * wgt);
                atomicAdd(orow + hcol + 1, acc[mf][nf][half * 2 + 1] * wgt);
            }
        }
    }
}

// ---------------- launch ----------------
extern "C" void kernel_launch(void* const* d_in, const int* in_sizes, int n_in,
                              void* d_out, int out_size) {
    const float* x    = (const float*)d_in[0];
    const float* w1   = (const float*)d_in[1];
    const float* w3   = (const float*)d_in[2];
    const float* w2   = (const float*)d_in[3];
    const float* gate = (const float*)d_in[4];
    float* out = (float*)d_out;
    float* out_lb = (out_size > TT * HH) ? (out + TT * HH) : nullptr;

    cudaFuncSetAttribute(k_gemmA, cudaFuncAttributeMaxDynamicSharedMemorySize, SMEM_DYN);
    cudaFuncSetAttribute(k_gemmB, cudaFuncAttributeMaxDynamicSharedMemorySize, SMEM_DYN);

    k_router<<<64, 256>>>(x, gate, out);
    k_build_tiles2<<<1, 256>>>(out_lb);
    k_gemmA<<<dim3(NTILES, 8), 256, SMEM_DYN>>>(w1, w3);
    k_gemmB<<<dim3(NTILES, 8), 256, SMEM_DYN>>>(w2, out);
}

// round 16
// speedup vs baseline: 1.0933x; 1.0933x over previous
#include <cuda_runtime.h>
#include <cuda_bf16.h>
#include <math.h>
#include <stdint.h>

#define TT 2048
#define HH 1024
#define DD 512
#define EE 64
#define TOPK 2
#define NTILES 128   // BM=64: sum ceil(cnt_e/64) <= 127

#define RS 20
#define RSB (RS * 4)
#define STG_U32 7680
#define STG_B   30720
#define SMEM_DYN (2 * STG_B)
#define NTASK_A (NTILES * 8)
#define NTASK   (2 * NTASK_A)

// ---------------- scratch ----------------
__device__ int   g_topk_i[TT * TOPK];
__device__ float g_topk_w[TT * TOPK];
__device__ int   g_counts[EE];
__device__ int   g_list[EE * TT];
__device__ float g_usage_partial[64 * EE];
__device__ int2  g_tiles[NTILES];
__device__ int   g_task;
__device__ int   g_doneA[NTILES];
__device__ __nv_bfloat16 g_xh[TT * HH], g_xl[TT * HH];
__device__ __nv_bfloat16 g_ah[TT * TOPK * DD], g_al[TT * TOPK * DD];

// ---------------- helpers ----------------
__device__ __forceinline__ uint32_t pack_bf2(__nv_bfloat16 a, __nv_bfloat16 b) {
    return (uint32_t)__bfloat16_as_ushort(a) | ((uint32_t)__bfloat16_as_ushort(b) << 16);
}
__device__ __forceinline__ void split32(float v, __nv_bfloat16& h, __nv_bfloat16& l) {
    h = __float2bfloat16(v);
    l = __float2bfloat16(v - __bfloat162float(h));
}
__device__ __forceinline__ void split_pack(float a, float b, uint32_t& hi, uint32_t& lo) {
    __nv_bfloat16 h0, h1, l0, l1;
    split32(a, h0, l0); split32(b, h1, l1);
    hi = pack_bf2(h0, h1); lo = pack_bf2(l0, l1);
}
__device__ __forceinline__ void mma16816(float* d, const uint32_t* a, const uint32_t* b) {
    asm volatile("mma.sync.aligned.m16n8k16.row.col.f32.bf16.bf16.f32 "
        "{%0,%1,%2,%3}, {%4,%5,%6,%7}, {%8,%9}, {%0,%1,%2,%3};"
        : "+f"(d[0]), "+f"(d[1]), "+f"(d[2]), "+f"(d[3])
        : "r"(a[0]), "r"(a[1]), "r"(a[2]), "r"(a[3]), "r"(b[0]), "r"(b[1]));
}
__device__ __forceinline__ uint32_t smaddr(const void* p) {
    return (uint32_t)__cvta_generic_to_shared(p);
}
__device__ __forceinline__ void ldm_x4(uint32_t* r, uint32_t a) {
    asm volatile("ldmatrix.sync.aligned.m8n8.x4.shared.b16 {%0,%1,%2,%3}, [%4];"
                 : "=r"(r[0]), "=r"(r[1]), "=r"(r[2]), "=r"(r[3]) : "r"(a));
}

// ---------------- router (+ out-zeroing + x-split; NO atomics) ----------------
__global__ __launch_bounds__(256) void k_router(const float* __restrict__ x,
                                                const float* __restrict__ gate,
                                                float* __restrict__ out) {
    __shared__ float Xs[32][33];
    __shared__ float Gs[32][68];
    __shared__ float Ls[32][65];
    __shared__ float sM[32], sInv[32];

    const int t0 = blockIdx.x * 32;
    const int tid = threadIdx.x;
    const int tx = tid & 15, ty = tid >> 4;

    {
        float4* ob = ((float4*)out) + (size_t)blockIdx.x * 8192;
        float4 z = make_float4(0.f, 0.f, 0.f, 0.f);
#pragma unroll
        for (int i = 0; i < 32; i++) ob[tid + i * 256] = z;
    }

    float acc[2][4];
#pragma unroll
    for (int i = 0; i < 2; i++)
#pragma unroll
        for (int j = 0; j < 4; j++) acc[i][j] = 0.f;

    for (int k0 = 0; k0 < HH; k0 += 32) {
        {
            int m = tid >> 3, k4 = (tid & 7) * 4;
            float4 v = *(const float4*)(x + (size_t)(t0 + m) * HH + k0 + k4);
            Xs[m][k4 + 0] = v.x; Xs[m][k4 + 1] = v.y;
            Xs[m][k4 + 2] = v.z; Xs[m][k4 + 3] = v.w;
            uint2 ph, pl;
            split_pack(v.x, v.y, ph.x, pl.x);
            split_pack(v.z, v.w, ph.y, pl.y);
            size_t off = (size_t)(t0 + m) * HH + k0 + k4;
            *(uint2*)(g_xh + off) = ph;
            *(uint2*)(g_xl + off) = pl;
        }
        {
            int k = tid >> 4, j4 = (tid & 15) * 4;
#pragma unroll
            for (int r = 0; r < 2; r++) {
                float4 v = *(const float4*)(gate + (size_t)(k0 + k + r * 16) * EE + j4);
                *(float4*)&Gs[k + r * 16][j4] = v;
            }
        }
        __syncthreads();
#pragma unroll
        for (int kk = 0; kk < 32; kk++) {
            float a0 = Xs[ty * 2 + 0][kk];
            float a1 = Xs[ty * 2 + 1][kk];
            float4 b = *(float4*)&Gs[kk][tx * 4];
            acc[0][0] += a0 * b.x; acc[0][1] += a0 * b.y; acc[0][2] += a0 * b.z; acc[0][3] += a0 * b.w;
            acc[1][0] += a1 * b.x; acc[1][1] += a1 * b.y; acc[1][2] += a1 * b.z; acc[1][3] += a1 * b.w;
        }
        __syncthreads();
    }
#pragma unroll
    for (int mi = 0; mi < 2; mi++)
#pragma unroll
        for (int ni = 0; ni < 4; ni++)
            Ls[ty * 2 + mi][tx * 4 + ni] = acc[mi][ni];
    __syncthreads();

    if (tid < 32) {
        int t = t0 + tid;
        float m1 = -1e30f, m2 = -1e30f;
        int i1 = -1, i2 = -1;
        for (int e = 0; e < EE; e++) {
            float l = Ls[tid][e];
            if (l > m1) { m2 = m1; i2 = i1; m1 = l; i1 = e; }
            else if (l > m2) { m2 = l; i2 = e; }
        }
        float den = 0.f;
        for (int e = 0; e < EE; e++) den += __expf(Ls[tid][e] - m1);
        sM[tid] = m1; sInv[tid] = 1.f / den;
        float e2 = __expf(m2 - m1);
        float s = 1.f + e2;
        g_topk_i[t * 2 + 0] = i1;
        g_topk_i[t * 2 + 1] = i2;
        g_topk_w[t * 2 + 0] = 1.f / s;
        g_topk_w[t * 2 + 1] = e2 / s;
    }
    __syncthreads();

    if (tid < EE) {
        float s = 0.f;
        for (int r = 0; r < 32; r++)
            s += __expf(Ls[r][tid] - sM[r]) * sInv[r];
        g_usage_partial[blockIdx.x * EE + tid] = s;
    }
}

// ---------------- list-build + tiles + lb + task/done reset; 1 block, 256 thr ----------------
__global__ void k_build_tiles2(float* __restrict__ out_lb) {
    __shared__ int sCnt[EE];
    __shared__ int sBase[EE];
    __shared__ int sPos[EE];
    __shared__ float red[64];

    const int tid = threadIdx.x;
    if (tid < EE) { sCnt[tid] = 0; sPos[tid] = 0; }
    for (int i = tid; i < NTILES; i += 256) {
        g_tiles[i] = make_int2(-1, 0);
        g_doneA[i] = 0;
    }
    if (tid == 0) g_task = 0;
    __syncthreads();

    for (int i = tid; i < TT * TOPK; i += 256)
        atomicAdd(&sCnt[g_topk_i[i]], 1);
    __syncthreads();

    if (tid == 0) {
        int a = 0;
        for (int e = 0; e < EE; e++) { sBase[e] = a; a += (sCnt[e] + 63) >> 6; }
    }
    __syncthreads();

    for (int i = tid; i < TT * TOPK; i += 256) {
        int e = g_topk_i[i];
        int pos = atomicAdd(&sPos[e], 1);
        g_list[e * TT + pos] = i;
    }

    if (tid < EE) {
        int e = tid;
        g_counts[e] = sCnt[e];
        int nt = (sCnt[e] + 63) >> 6;
        int base = sBase[e];
        for (int i = 0; i < nt; i++) g_tiles[base + i] = make_int2(e, i * 64);
        float s = 0.f;
        for (int b = 0; b < 64; b++) s += g_usage_partial[b * EE + e];
        float u = s / (float)TT;
        red[e] = u * u;
    }
    __syncthreads();
    if (tid < 64) {
        for (int off = 32; off > 0; off >>= 1) {
            if (tid < off) red[tid] += red[tid + off];
            __syncwarp(0xFFFFFFFF);
        }
        if (tid == 0 && out_lb) *out_lb = (float)EE * red[0];
    }
}

// ================= GEMM A body: BM=64, BN=64, BK=32 =================
__device__ __forceinline__ void doA(int tileIdx, int yb,
                                    const float* __restrict__ w1,
                                    const float* __restrict__ w3,
                                    uint32_t* smp, int* sPair) {
    int2 tile = g_tiles[tileIdx];
    if (tile.x < 0) return;
    const int e = tile.x, t0 = tile.y;
    const int d0 = yb * 64;
    const int tid = threadIdx.x;
    const int lane = tid & 31, wid = tid >> 5;
    const int g = lane >> 2, q = lane & 3;
    const int warp_m = wid & 1, warp_n = wid >> 1;
    const int cnt = g_counts[e];

    uint32_t* XSh = smp;
    uint32_t* XSl = smp + 1280;
    uint32_t* W1h = smp + 2560;
    uint32_t* W1l = smp + 3840;
    uint32_t* W3h = smp + 5120;
    uint32_t* W3l = smp + 6400;

    if (tid < 64) {
        int idx = t0 + tid;
        sPair[tid] = (idx < cnt) ? g_list[e * TT + idx] : -1;
    }
    __syncthreads();

    const float* w1e = w1 + (size_t)e * HH * DD;
    const float* w3e = w3 + (size_t)e * HH * DD;

    const int xrow = tid >> 2, xkp = (tid & 3) * 4;
    const int xp = sPair[xrow];
    const __nv_bfloat16* xsh = (xp >= 0) ? (g_xh + (size_t)(xp >> 1) * HH + xkp * 2) : 0;
    const __nv_bfloat16* xsl = (xp >= 0) ? (g_xl + (size_t)(xp >> 1) * HH + xkp * 2) : 0;
    const int dd = tid & 63, q4 = tid >> 6;
    const float* w1p = w1e + (size_t)(q4 * 8) * DD + d0 + dd;
    const float* w3p = w3e + (size_t)(q4 * 8) * DD + d0 + dd;

    const int arow = warp_m * 32 + (lane & 15);
    const int acof = (lane >> 4) * 4;
    const uint32_t aXh = smaddr(&XSh[arow * RS + acof]);
    const uint32_t aXl = smaddr(&XSl[arow * RS + acof]);
    const int nrow = warp_n * 16 + (lane >> 4) * 8 + (lane & 7);
    const int ncof = ((lane >> 3) & 1) * 4;
    const uint32_t aW1h = smaddr(&W1h[nrow * RS + ncof]);
    const uint32_t aW1l = smaddr(&W1l[nrow * RS + ncof]);
    const uint32_t aW3h = smaddr(&W3h[nrow * RS + ncof]);
    const uint32_t aW3l = smaddr(&W3l[nrow * RS + ncof]);

    float acc1[2][2][4], acc3[2][2][4];
#pragma unroll
    for (int a = 0; a < 2; a++)
#pragma unroll
        for (int b = 0; b < 2; b++)
#pragma unroll
            for (int c = 0; c < 4; c++) { acc1[a][b][c] = 0.f; acc3[a][b][c] = 0.f; }

    uint4 pvh, pvl;
    float pw1[8], pw3[8];
#define GA_LOAD(K0)                                                        \
    {                                                                      \
        pvh = make_uint4(0, 0, 0, 0); pvl = make_uint4(0, 0, 0, 0);        \
        if (xp >= 0) {                                                     \
            pvh = *(const uint4*)(xsh + (K0));                             \
            pvl = *(const uint4*)(xsl + (K0));                             \
        }                                                                  \
        const float* p1 = w1p + (size_t)(K0) * DD;                         \
        const float* p3 = w3p + (size_t)(K0) * DD;                         \
        _Pragma("unroll")                                                  \
        for (int i = 0; i < 8; i++) { pw1[i] = p1[i * DD]; pw3[i] = p3[i * DD]; } \
    }

    GA_LOAD(0)
    const int NC = HH / 32;
    for (int c = 0; c < NC; c++) {
        const int bo = (c & 1) * STG_U32;
        const uint32_t bob = (uint32_t)(c & 1) * STG_B;
        *(uint4*)&XSh[bo + xrow * RS + xkp] = pvh;
        *(uint4*)&XSl[bo + xrow * RS + xkp] = pvl;
        {
            uint32_t h[4], l[4];
            split_pack(pw1[0], pw1[1], h[0], l[0]);
            split_pack(pw1[2], pw1[3], h[1], l[1]);
            split_pack(pw1[4], pw1[5], h[2], l[2]);
            split_pack(pw1[6], pw1[7], h[3], l[3]);
            *(uint4*)&W1h[bo + dd * RS + q4 * 4] = make_uint4(h[0], h[1], h[2], h[3]);
            *(uint4*)&W1l[bo + dd * RS + q4 * 4] = make_uint4(l[0], l[1], l[2], l[3]);
            split_pack(pw3[0], pw3[1], h[0], l[0]);
            split_pack(pw3[2], pw3[3], h[1], l[1]);
            split_pack(pw3[4], pw3[5], h[2], l[2]);
            split_pack(pw3[6], pw3[7], h[3], l[3]);
            *(uint4*)&W3h[bo + dd * RS + q4 * 4] = make_uint4(h[0], h[1], h[2], h[3]);
            *(uint4*)&W3l[bo + dd * RS + q4 * 4] = make_uint4(l[0], l[1], l[2], l[3]);
        }
        if (c + 1 < NC) GA_LOAD((c + 1) * 32)
        __syncthreads();

#pragma unroll
        for (int s = 0; s < 2; s++) {
            const uint32_t s32 = bob + s * 32;
            uint32_t ah[2][4], al[2][4];
            ldm_x4(ah[0], aXh + s32);
            ldm_x4(ah[1], aXh + 16 * RSB + s32);
            ldm_x4(al[0], aXl + s32);
            ldm_x4(al[1], aXl + 16 * RSB + s32);
            uint32_t b1h[4], b1l[4], b3h[4], b3l[4];
            ldm_x4(b1h, aW1h + s32);
            ldm_x4(b1l, aW1l + s32);
            ldm_x4(b3h, aW3h + s32);
            ldm_x4(b3l, aW3l + s32);
#pragma unroll
            for (int nf = 0; nf < 2; nf++) {
#pragma unroll
                for (int mf = 0; mf < 2; mf++) {
                    mma16816(acc1[mf][nf], ah[mf], b1h + nf * 2);
                    mma16816(acc1[mf][nf], ah[mf], b1l + nf * 2);
                    mma16816(acc1[mf][nf], al[mf], b1h + nf * 2);
                    mma16816(acc3[mf][nf], ah[mf], b3h + nf * 2);
                    mma16816(acc3[mf][nf], ah[mf], b3l + nf * 2);
                    mma16816(acc3[mf][nf], al[mf], b3h + nf * 2);
                }
            }
        }
    }

#pragma unroll
    for (int mf = 0; mf < 2; mf++) {
        int rbase = warp_m * 32 + mf * 16 + g;
#pragma unroll
        for (int half = 0; half < 2; half++) {
            int r = rbase + half * 8;
            int p = sPair[r];
            if (p < 0) continue;
#pragma unroll
            for (int nf = 0; nf < 2; nf++) {
                int dcol = d0 + warp_n * 16 + nf * 8 + q * 2;
                float h0 = acc1[mf][nf][half * 2 + 0], g0 = acc3[mf][nf][half * 2 + 0];
                float h1 = acc1[mf][nf][half * 2 + 1], g1 = acc3[mf][nf][half * 2 + 1];
                float o0 = h0 * g0 / (1.f + __expf(-h0));
                float o1 = h1 * g1 / (1.f + __expf(-h1));
                uint32_t hi, lo;
                split_pack(o0, o1, hi, lo);
                *(uint32_t*)(g_ah + (size_t)p * DD + dcol) = hi;
                *(uint32_t*)(g_al + (size_t)p * DD + dcol) = lo;
            }
        }
    }

    // signal completion for dependency tracking
    __threadfence();
    __syncthreads();
    if (tid == 0) atomicAdd(&g_doneA[tileIdx], 1);
}

// ================= GEMM B body: BM=64, BN=128, BK=32 =================
__device__ __forceinline__ void doB(int tileIdx, int yb,
                                    const float* __restrict__ w2,
                                    float* __restrict__ out,
                                    uint32_t* smp, int* sPair, float* sW) {
    int2 tile = g_tiles[tileIdx];
    if (tile.x < 0) return;
    const int e = tile.x, t0 = tile.y;
    const int h0 = yb * 128;
    const int tid = threadIdx.x;
    const int lane = tid & 31, wid = tid >> 5;
    const int g = lane >> 2, q = lane & 3;
    const int warp_m = wid & 1, warp_n = wid >> 1;
    const int cnt = g_counts[e];

    uint32_t* ASh = smp;
    uint32_t* ASl = smp + 1280;
    uint32_t* W2h = smp + 2560;
    uint32_t* W2l = smp + 5120;

    // wait for all 8 gemmA y-blocks of this tile
    if (tid == 0) {
        while (atomicAdd(&g_doneA[tileIdx], 0) < 8) { }
        __threadfence();
    }
    __syncthreads();

    if (tid < 64) {
        int idx = t0 + tid;
        int p = (idx < cnt) ? g_list[e * TT + idx] : -1;
        sPair[tid] = p;
        sW[tid] = (p >= 0) ? g_topk_w[p] : 0.f;
    }
    __syncthreads();

    const float* w2e = w2 + (size_t)e * DD * HH;

    const int xrow = tid >> 2, xkp = (tid & 3) * 4;
    const int xp = sPair[xrow];
    const __nv_bfloat16* ash = (xp >= 0) ? (g_ah + (size_t)xp * DD + xkp * 2) : 0;
    const __nv_bfloat16* asl = (xp >= 0) ? (g_al + (size_t)xp * DD + xkp * 2) : 0;
    const int hh = tid & 127, qh = tid >> 7;
    const float* w2p = w2e + (size_t)(qh * 16) * HH + h0 + hh;

    const int arow = warp_m * 32 + (lane & 15);
    const int acof = (lane >> 4) * 4;
    const uint32_t aAh = smaddr(&ASh[arow * RS + acof]);
    const uint32_t aAl = smaddr(&ASl[arow * RS + acof]);
    const int nrow = warp_n * 32 + (lane >> 4) * 8 + (lane & 7);
    const int ncof = ((lane >> 3) & 1) * 4;
    const uint32_t aW2h = smaddr(&W2h[nrow * RS + ncof]);
    const uint32_t aW2l = smaddr(&W2l[nrow * RS + ncof]);

    float acc[2][4][4];
#pragma unroll
    for (int a = 0; a < 2; a++)
#pragma unroll
        for (int b = 0; b < 4; b++)
#pragma unroll
            for (int c = 0; c < 4; c++) acc[a][b][c] = 0.f;

    uint4 pvh, pvl;
    float pw2[16];
#define GB_LOAD(K0)                                                        \
    {                                                                      \
        pvh = make_uint4(0, 0, 0, 0); pvl = make_uint4(0, 0, 0, 0);        \
        if (xp >= 0) {                                                     \
            pvh = *(const uint4*)(ash + (K0));                             \
            pvl = *(const uint4*)(asl + (K0));                             \
        }                                                                  \
        const float* p2 = w2p + (size_t)(K0) * HH;                         \
        _Pragma("unroll")                                                  \
        for (int i = 0; i < 16; i++) pw2[i] = p2[i * HH];                  \
    }

    GB_LOAD(0)
    const int NC = DD / 32;
    for (int c = 0; c < NC; c++) {
        const int bo = (c & 1) * STG_U32;
        const uint32_t bob = (uint32_t)(c & 1) * STG_B;
        *(uint4*)&ASh[bo + xrow * RS + xkp] = pvh;
        *(uint4*)&ASl[bo + xrow * RS + xkp] = pvl;
        {
            uint32_t h[8], l[8];
#pragma unroll
            for (int j = 0; j < 8; j++) split_pack(pw2[2 * j], pw2[2 * j + 1], h[j], l[j]);
            *(uint4*)&W2h[bo + hh * RS + qh * 8 + 0] = make_uint4(h[0], h[1], h[2], h[3]);
            *(uint4*)&W2h[bo + hh * RS + qh * 8 + 4] = make_uint4(h[4], h[5], h[6], h[7]);
            *(uint4*)&W2l[bo + hh * RS + qh * 8 + 0] = make_uint4(l[0], l[1], l[2], l[3]);
            *(uint4*)&W2l[bo + hh * RS + qh * 8 + 4] = make_uint4(l[4], l[5], l[6], l[7]);
        }
        if (c + 1 < NC) GB_LOAD((c + 1) * 32)
        __syncthreads();

#pragma unroll
        for (int s = 0; s < 2; s++) {
            const uint32_t s32 = bob + s * 32;
            uint32_t ah[2][4], al[2][4];
            ldm_x4(ah[0], aAh + s32);
            ldm_x4(ah[1], aAh + 16 * RSB + s32);
            ldm_x4(al[0], aAl + s32);
            ldm_x4(al[1], aAl + 16 * RSB + s32);
#pragma unroll
            for (int np = 0; np < 2; np++) {
                uint32_t bh[4], bl[4];
                ldm_x4(bh, aW2h + np * 16 * RSB + s32);
                ldm_x4(bl, aW2l + np * 16 * RSB + s32);
#pragma unroll
                for (int sub = 0; sub < 2; sub++) {
                    int nf = np * 2 + sub;
#pragma unroll
                    for (int mf = 0; mf < 2; mf++) {
                        mma16816(acc[mf][nf], ah[mf], bh + sub * 2);
                        mma16816(acc[mf][nf], ah[mf], bl + sub * 2);
                        mma16816(acc[mf][nf], al[mf], bh + sub * 2);
                    }
                }
            }
        }
    }

#pragma unroll
    for (int mf = 0; mf < 2; mf++) {
        int rbase = warp_m * 32 + mf * 16 + g;
#pragma unroll
        for (int half = 0; half < 2; half++) {
            int r = rbase + half * 8;
            int p = sPair[r];
            if (p < 0) continue;
            int tok = p >> 1;
            float wgt = sW[r];
            float* orow = out + (size_t)tok * HH;
#pragma unroll
            for (int nf = 0; nf < 4; nf++) {
                int hcol = h0 + warp_n * 32 + nf * 8 + q * 2;
                atomicAdd(orow + hcol + 0, acc[mf][nf][half * 2 + 0] * wgt);
                atomicAdd(orow + hcol + 1, acc[mf][nf][half * 2 + 1] * wgt);
            }
        }
    }
}

// ================= fused persistent GEMM kernel =================
__global__ __launch_bounds__(256, 2) void k_fused(const float* __restrict__ w1,
                                                  const float* __restrict__ w3,
                                                  const float* __restrict__ w2,
                                                  float* __restrict__ out) {
    extern __shared__ uint32_t smp[];
    __shared__ int sPair[64];
    __shared__ float sW[64];
    __shared__ int sTask;

    for (;;) {
        __syncthreads();   // smem reuse + sTask protection
        if (threadIdx.x == 0) sTask = atomicAdd(&g_task, 1);
        __syncthreads();
        int t = sTask;
        if (t >= NTASK) return;
        if (t < NTASK_A) {
            doA(t >> 3, t & 7, w1, w3, smp, sPair);
        } else {
            t -= NTASK_A;
            doB(t >> 3, t & 7, w2, out, smp, sPair, sW);
        }
    }
}

// ---------------- launch ----------------
extern "C" void kernel_launch(void* const* d_in, const int* in_sizes, int n_in,
                              void* d_out, int out_size) {
    const float* x    = (const float*)d_in[0];
    const float* w1   = (const float*)d_in[1];
    const float* w3   = (const float*)d_in[2];
    const float* w2   = (const float*)d_in[3];
    const float* gate = (const float*)d_in[4];
    float* out = (float*)d_out;
    float* out_lb = (out_size > TT * HH) ? (out + TT * HH) : nullptr;

    cudaFuncSetAttribute(k_fused, cudaFuncAttributeMaxDynamicSharedMemorySize, SMEM_DYN);

    k_router<<<64, 256>>>(x, gate, out);
    k_build_tiles2<<<1, 256>>>(out_lb);
    k_fused<<<1024, 256, SMEM_DYN>>>(w1, w3, w2, out);
}

// round 17
// speedup vs baseline: 1.2360x; 1.1305x over previous
#include <cuda_runtime.h>
#include <cuda_bf16.h>
#include <math.h>
#include <stdint.h>

#define TT 2048
#define HH 1024
#define DD 512
#define EE 64
#define TOPK 2
#define NTILES 128   // BM=64: sum ceil(cnt_e/64) <= 127

#define RS 20
#define RSB (RS * 4)
#define STG_U32 7680
#define STG_B   30720
#define SMEM_DYN (2 * STG_B)
#define NTASK_A (NTILES * 8)
#define NTASK   (2 * NTASK_A)

// ---------------- scratch ----------------
__device__ int   g_topk_i[TT * TOPK];
__device__ float g_topk_w[TT * TOPK];
__device__ int   g_counts[EE];
__device__ int   g_list[EE * TT];
__device__ float g_usage_partial[64 * EE];
__device__ float g_part[4 * TT * EE];          // partial logits per K-quarter
__device__ int2  g_tiles[NTILES];
__device__ int   g_task;
__device__ int   g_doneA[NTILES];
__device__ __nv_bfloat16 g_xh[TT * HH], g_xl[TT * HH];
__device__ __nv_bfloat16 g_ah[TT * TOPK * DD], g_al[TT * TOPK * DD];

// ---------------- helpers ----------------
__device__ __forceinline__ uint32_t pack_bf2(__nv_bfloat16 a, __nv_bfloat16 b) {
    return (uint32_t)__bfloat16_as_ushort(a) | ((uint32_t)__bfloat16_as_ushort(b) << 16);
}
__device__ __forceinline__ void split32(float v, __nv_bfloat16& h, __nv_bfloat16& l) {
    h = __float2bfloat16(v);
    l = __float2bfloat16(v - __bfloat162float(h));
}
__device__ __forceinline__ void split_pack(float a, float b, uint32_t& hi, uint32_t& lo) {
    __nv_bfloat16 h0, h1, l0, l1;
    split32(a, h0, l0); split32(b, h1, l1);
    hi = pack_bf2(h0, h1); lo = pack_bf2(l0, l1);
}
__device__ __forceinline__ void mma16816(float* d, const uint32_t* a, const uint32_t* b) {
    asm volatile("mma.sync.aligned.m16n8k16.row.col.f32.bf16.bf16.f32 "
        "{%0,%1,%2,%3}, {%4,%5,%6,%7}, {%8,%9}, {%0,%1,%2,%3};"
        : "+f"(d[0]), "+f"(d[1]), "+f"(d[2]), "+f"(d[3])
        : "r"(a[0]), "r"(a[1]), "r"(a[2]), "r"(a[3]), "r"(b[0]), "r"(b[1]));
}
__device__ __forceinline__ uint32_t smaddr(const void* p) {
    return (uint32_t)__cvta_generic_to_shared(p);
}
__device__ __forceinline__ void ldm_x4(uint32_t* r, uint32_t a) {
    asm volatile("ldmatrix.sync.aligned.m8n8.x4.shared.b16 {%0,%1,%2,%3}, [%4];"
                 : "=r"(r[0]), "=r"(r[1]), "=r"(r[2]), "=r"(r[3]) : "r"(a));
}

// ---------------- router GEMM: partial logits over K-quarter + x-split + out-zero ----------------
__global__ __launch_bounds__(256) void k_routerG(const float* __restrict__ x,
                                                 const float* __restrict__ gate,
                                                 float* __restrict__ out) {
    __shared__ float Xs[32][33];
    __shared__ float Gs[32][68];

    const int tb = blockIdx.x, kq = blockIdx.y;
    const int t0 = tb * 32;
    const int kbase = kq * 256;
    const int tid = threadIdx.x;
    const int tx = tid & 15, ty = tid >> 4;

    // zero out: each of the 256 blocks zeroes 1/256 of out (8192 floats)
    {
        float4* ob = ((float4*)out) + (size_t)(tb * 4 + kq) * 2048;
        float4 z = make_float4(0.f, 0.f, 0.f, 0.f);
#pragma unroll
        for (int i = 0; i < 8; i++) ob[tid + i * 256] = z;
    }

    float acc[2][4];
#pragma unroll
    for (int i = 0; i < 2; i++)
#pragma unroll
        for (int j = 0; j < 4; j++) acc[i][j] = 0.f;

    for (int k0 = kbase; k0 < kbase + 256; k0 += 32) {
        {
            int m = tid >> 3, k4 = (tid & 7) * 4;
            float4 v = *(const float4*)(x + (size_t)(t0 + m) * HH + k0 + k4);
            Xs[m][k4 + 0] = v.x; Xs[m][k4 + 1] = v.y;
            Xs[m][k4 + 2] = v.z; Xs[m][k4 + 3] = v.w;
            // fused split of this slice of x
            uint2 ph, pl;
            split_pack(v.x, v.y, ph.x, pl.x);
            split_pack(v.z, v.w, ph.y, pl.y);
            size_t off = (size_t)(t0 + m) * HH + k0 + k4;
            *(uint2*)(g_xh + off) = ph;
            *(uint2*)(g_xl + off) = pl;
        }
        {
            int k = tid >> 4, j4 = (tid & 15) * 4;
#pragma unroll
            for (int r = 0; r < 2; r++) {
                float4 v = *(const float4*)(gate + (size_t)(k0 + k + r * 16) * EE + j4);
                *(float4*)&Gs[k + r * 16][j4] = v;
            }
        }
        __syncthreads();
#pragma unroll
        for (int kk = 0; kk < 32; kk++) {
            float a0 = Xs[ty * 2 + 0][kk];
            float a1 = Xs[ty * 2 + 1][kk];
            float4 b = *(float4*)&Gs[kk][tx * 4];
            acc[0][0] += a0 * b.x; acc[0][1] += a0 * b.y; acc[0][2] += a0 * b.z; acc[0][3] += a0 * b.w;
            acc[1][0] += a1 * b.x; acc[1][1] += a1 * b.y; acc[1][2] += a1 * b.z; acc[1][3] += a1 * b.w;
        }
        __syncthreads();
    }

    // write partial logits
    float* dst = g_part + (size_t)kq * TT * EE + (size_t)t0 * EE;
#pragma unroll
    for (int mi = 0; mi < 2; mi++) {
        int row = ty * 2 + mi;
        *(float4*)&dst[row * EE + tx * 4] = make_float4(acc[mi][0], acc[mi][1], acc[mi][2], acc[mi][3]);
    }
}

// ---------------- top-k + softmax + usage partials ----------------
__global__ __launch_bounds__(256) void k_topk() {
    __shared__ float Ls[32][65];
    __shared__ float sM[32], sInv[32];

    const int t0 = blockIdx.x * 32;
    const int tid = threadIdx.x;

    // sum 4 K-partials in fixed order; 512 float4 total, 2 per thread
#pragma unroll
    for (int j = 0; j < 2; j++) {
        int lin4 = tid * 2 + j;          // 0..511
        int row = lin4 >> 4;             // 0..31
        int c4 = (lin4 & 15) * 4;
        size_t off = (size_t)(t0 + row) * EE + c4;
        float4 p0 = *(const float4*)(g_part + 0 * TT * EE + off);
        float4 p1 = *(const float4*)(g_part + 1 * TT * EE + off);
        float4 p2 = *(const float4*)(g_part + 2 * TT * EE + off);
        float4 p3 = *(const float4*)(g_part + 3 * TT * EE + off);
        Ls[row][c4 + 0] = ((p0.x + p1.x) + p2.x) + p3.x;
        Ls[row][c4 + 1] = ((p0.y + p1.y) + p2.y) + p3.y;
        Ls[row][c4 + 2] = ((p0.z + p1.z) + p2.z) + p3.z;
        Ls[row][c4 + 3] = ((p0.w + p1.w) + p2.w) + p3.w;
    }
    __syncthreads();

    if (tid < 32) {
        int t = t0 + tid;
        float m1 = -1e30f, m2 = -1e30f;
        int i1 = -1, i2 = -1;
        for (int e = 0; e < EE; e++) {
            float l = Ls[tid][e];
            if (l > m1) { m2 = m1; i2 = i1; m1 = l; i1 = e; }
            else if (l > m2) { m2 = l; i2 = e; }
        }
        float den = 0.f;
        for (int e = 0; e < EE; e++) den += __expf(Ls[tid][e] - m1);
        sM[tid] = m1; sInv[tid] = 1.f / den;
        float e2 = __expf(m2 - m1);
        float s = 1.f + e2;
        g_topk_i[t * 2 + 0] = i1;
        g_topk_i[t * 2 + 1] = i2;
        g_topk_w[t * 2 + 0] = 1.f / s;
        g_topk_w[t * 2 + 1] = e2 / s;
    }
    __syncthreads();

    if (tid < EE) {
        float s = 0.f;
        for (int r = 0; r < 32; r++)
            s += __expf(Ls[r][tid] - sM[r]) * sInv[r];
        g_usage_partial[blockIdx.x * EE + tid] = s;
    }
}

// ---------------- list-build + tiles + lb + task/done reset; 1 block, 256 thr ----------------
__global__ void k_build_tiles2(float* __restrict__ out_lb) {
    __shared__ int sCnt[EE];
    __shared__ int sBase[EE];
    __shared__ int sPos[EE];
    __shared__ float red[64];

    const int tid = threadIdx.x;
    if (tid < EE) { sCnt[tid] = 0; sPos[tid] = 0; }
    for (int i = tid; i < NTILES; i += 256) {
        g_tiles[i] = make_int2(-1, 0);
        g_doneA[i] = 0;
    }
    if (tid == 0) g_task = 0;
    __syncthreads();

    for (int i = tid; i < TT * TOPK; i += 256)
        atomicAdd(&sCnt[g_topk_i[i]], 1);
    __syncthreads();

    if (tid == 0) {
        int a = 0;
        for (int e = 0; e < EE; e++) { sBase[e] = a; a += (sCnt[e] + 63) >> 6; }
    }
    __syncthreads();

    for (int i = tid; i < TT * TOPK; i += 256) {
        int e = g_topk_i[i];
        int pos = atomicAdd(&sPos[e], 1);
        g_list[e * TT + pos] = i;
    }

    if (tid < EE) {
        int e = tid;
        g_counts[e] = sCnt[e];
        int nt = (sCnt[e] + 63) >> 6;
        int base = sBase[e];
        for (int i = 0; i < nt; i++) g_tiles[base + i] = make_int2(e, i * 64);
        float s = 0.f;
        for (int b = 0; b < 64; b++) s += g_usage_partial[b * EE + e];
        float u = s / (float)TT;
        red[e] = u * u;
    }
    __syncthreads();
    if (tid < 64) {
        for (int off = 32; off > 0; off >>= 1) {
            if (tid < off) red[tid] += red[tid + off];
            __syncwarp(0xFFFFFFFF);
        }
        if (tid == 0 && out_lb) *out_lb = (float)EE * red[0];
    }
}

// ================= GEMM A body: BM=64, BN=64, BK=32 =================
__device__ __forceinline__ void doA(int tileIdx, int yb,
                                    const float* __restrict__ w1,
                                    const float* __restrict__ w3,
                                    uint32_t* smp, int* sPair) {
    int2 tile = g_tiles[tileIdx];
    if (tile.x < 0) return;
    const int e = tile.x, t0 = tile.y;
    const int d0 = yb * 64;
    const int tid = threadIdx.x;
    const int lane = tid & 31, wid = tid >> 5;
    const int g = lane >> 2, q = lane & 3;
    const int warp_m = wid & 1, warp_n = wid >> 1;
    const int cnt = g_counts[e];

    uint32_t* XSh = smp;
    uint32_t* XSl = smp + 1280;
    uint32_t* W1h = smp + 2560;
    uint32_t* W1l = smp + 3840;
    uint32_t* W3h = smp + 5120;
    uint32_t* W3l = smp + 6400;

    if (tid < 64) {
        int idx = t0 + tid;
        sPair[tid] = (idx < cnt) ? g_list[e * TT + idx] : -1;
    }
    __syncthreads();

    const float* w1e = w1 + (size_t)e * HH * DD;
    const float* w3e = w3 + (size_t)e * HH * DD;

    const int xrow = tid >> 2, xkp = (tid & 3) * 4;
    const int xp = sPair[xrow];
    const __nv_bfloat16* xsh = (xp >= 0) ? (g_xh + (size_t)(xp >> 1) * HH + xkp * 2) : 0;
    const __nv_bfloat16* xsl = (xp >= 0) ? (g_xl + (size_t)(xp >> 1) * HH + xkp * 2) : 0;
    const int dd = tid & 63, q4 = tid >> 6;
    const float* w1p = w1e + (size_t)(q4 * 8) * DD + d0 + dd;
    const float* w3p = w3e + (size_t)(q4 * 8) * DD + d0 + dd;

    const int arow = warp_m * 32 + (lane & 15);
    const int acof = (lane >> 4) * 4;
    const uint32_t aXh = smaddr(&XSh[arow * RS + acof]);
    const uint32_t aXl = smaddr(&XSl[arow * RS + acof]);
    const int nrow = warp_n * 16 + (lane >> 4) * 8 + (lane & 7);
    const int ncof = ((lane >> 3) & 1) * 4;
    const uint32_t aW1h = smaddr(&W1h[nrow * RS + ncof]);
    const uint32_t aW1l = smaddr(&W1l[nrow * RS + ncof]);
    const uint32_t aW3h = smaddr(&W3h[nrow * RS + ncof]);
    const uint32_t aW3l = smaddr(&W3l[nrow * RS + ncof]);

    float acc1[2][2][4], acc3[2][2][4];
#pragma unroll
    for (int a = 0; a < 2; a++)
#pragma unroll
        for (int b = 0; b < 2; b++)
#pragma unroll
            for (int c = 0; c < 4; c++) { acc1[a][b][c] = 0.f; acc3[a][b][c] = 0.f; }

    uint4 pvh, pvl;
    float pw1[8], pw3[8];
#define GA_LOAD(K0)                                                        \
    {                                                                      \
        pvh = make_uint4(0, 0, 0, 0); pvl = make_uint4(0, 0, 0, 0);        \
        if (xp >= 0) {                                                     \
            pvh = *(const uint4*)(xsh + (K0));                             \
            pvl = *(const uint4*)(xsl + (K0));                             \
        }                                                                  \
        const float* p1 = w1p + (size_t)(K0) * DD;                         \
        const float* p3 = w3p + (size_t)(K0) * DD;                         \
        _Pragma("unroll")                                                  \
        for (int i = 0; i < 8; i++) { pw1[i] = p1[i * DD]; pw3[i] = p3[i * DD]; } \
    }

    GA_LOAD(0)
    const int NC = HH / 32;
    for (int c = 0; c < NC; c++) {
        const int bo = (c & 1) * STG_U32;
        const uint32_t bob = (uint32_t)(c & 1) * STG_B;
        *(uint4*)&XSh[bo + xrow * RS + xkp] = pvh;
        *(uint4*)&XSl[bo + xrow * RS + xkp] = pvl;
        {
            uint32_t h[4], l[4];
            split_pack(pw1[0], pw1[1], h[0], l[0]);
            split_pack(pw1[2], pw1[3], h[1], l[1]);
            split_pack(pw1[4], pw1[5], h[2], l[2]);
            split_pack(pw1[6], pw1[7], h[3], l[3]);
            *(uint4*)&W1h[bo + dd * RS + q4 * 4] = make_uint4(h[0], h[1], h[2], h[3]);
            *(uint4*)&W1l[bo + dd * RS + q4 * 4] = make_uint4(l[0], l[1], l[2], l[3]);
            split_pack(pw3[0], pw3[1], h[0], l[0]);
            split_pack(pw3[2], pw3[3], h[1], l[1]);
            split_pack(pw3[4], pw3[5], h[2], l[2]);
            split_pack(pw3[6], pw3[7], h[3], l[3]);
            *(uint4*)&W3h[bo + dd * RS + q4 * 4] = make_uint4(h[0], h[1], h[2], h[3]);
            *(uint4*)&W3l[bo + dd * RS + q4 * 4] = make_uint4(l[0], l[1], l[2], l[3]);
        }
        if (c + 1 < NC) GA_LOAD((c + 1) * 32)
        __syncthreads();

#pragma unroll
        for (int s = 0; s < 2; s++) {
            const uint32_t s32 = bob + s * 32;
            uint32_t ah[2][4], al[2][4];
            ldm_x4(ah[0], aXh + s32);
            ldm_x4(ah[1], aXh + 16 * RSB + s32);
            ldm_x4(al[0], aXl + s32);
            ldm_x4(al[1], aXl + 16 * RSB + s32);
            uint32_t b1h[4], b1l[4], b3h[4], b3l[4];
            ldm_x4(b1h, aW1h + s32);
            ldm_x4(b1l, aW1l + s32);
            ldm_x4(b3h, aW3h + s32);
            ldm_x4(b3l, aW3l + s32);
#pragma unroll
            for (int nf = 0; nf < 2; nf++) {
#pragma unroll
                for (int mf = 0; mf < 2; mf++) {
                    mma16816(acc1[mf][nf], ah[mf], b1h + nf * 2);
                    mma16816(acc1[mf][nf], ah[mf], b1l + nf * 2);
                    mma16816(acc1[mf][nf], al[mf], b1h + nf * 2);
                    mma16816(acc3[mf][nf], ah[mf], b3h + nf * 2);
                    mma16816(acc3[mf][nf], ah[mf], b3l + nf * 2);
                    mma16816(acc3[mf][nf], al[mf], b3h + nf * 2);
                }
            }
        }
    }

#pragma unroll
    for (int mf = 0; mf < 2; mf++) {
        int rbase = warp_m * 32 + mf * 16 + g;
#pragma unroll
        for (int half = 0; half < 2; half++) {
            int r = rbase + half * 8;
            int p = sPair[r];
            if (p < 0) continue;
#pragma unroll
            for (int nf = 0; nf < 2; nf++) {
                int dcol = d0 + warp_n * 16 + nf * 8 + q * 2;
                float h0 = acc1[mf][nf][half * 2 + 0], g0 = acc3[mf][nf][half * 2 + 0];
                float h1 = acc1[mf][nf][half * 2 + 1], g1 = acc3[mf][nf][half * 2 + 1];
                float o0 = h0 * g0 / (1.f + __expf(-h0));
                float o1 = h1 * g1 / (1.f + __expf(-h1));
                uint32_t hi, lo;
                split_pack(o0, o1, hi, lo);
                *(uint32_t*)(g_ah + (size_t)p * DD + dcol) = hi;
                *(uint32_t*)(g_al + (size_t)p * DD + dcol) = lo;
            }
        }
    }

    __threadfence();
    __syncthreads();
    if (tid == 0) atomicAdd(&g_doneA[tileIdx], 1);
}

// ================= GEMM B body: BM=64, BN=128, BK=32 =================
__device__ __forceinline__ void doB(int tileIdx, int yb,
                                    const float* __restrict__ w2,
                                    float* __restrict__ out,
                                    uint32_t* smp, int* sPair, float* sW) {
    int2 tile = g_tiles[tileIdx];
    if (tile.x < 0) return;
    const int e = tile.x, t0 = tile.y;
    const int h0 = yb * 128;
    const int tid = threadIdx.x;
    const int lane = tid & 31, wid = tid >> 5;
    const int g = lane >> 2, q = lane & 3;
    const int warp_m = wid & 1, warp_n = wid >> 1;
    const int cnt = g_counts[e];

    uint32_t* ASh = smp;
    uint32_t* ASl = smp + 1280;
    uint32_t* W2h = smp + 2560;
    uint32_t* W2l = smp + 5120;

    if (tid == 0) {
        while (atomicAdd(&g_doneA[tileIdx], 0) < 8) { }
        __threadfence();
    }
    __syncthreads();

    if (tid < 64) {
        int idx = t0 + tid;
        int p = (idx < cnt) ? g_list[e * TT + idx] : -1;
        sPair[tid] = p;
        sW[tid] = (p >= 0) ? g_topk_w[p] : 0.f;
    }
    __syncthreads();

    const float* w2e = w2 + (size_t)e * DD * HH;

    const int xrow = tid >> 2, xkp = (tid & 3) * 4;
    const int xp = sPair[xrow];
    const __nv_bfloat16* ash = (xp >= 0) ? (g_ah + (size_t)xp * DD + xkp * 2) : 0;
    const __nv_bfloat16* asl = (xp >= 0) ? (g_al + (size_t)xp * DD + xkp * 2) : 0;
    const int hh = tid & 127, qh = tid >> 7;
    const float* w2p = w2e + (size_t)(qh * 16) * HH + h0 + hh;

    const int arow = warp_m * 32 + (lane & 15);
    const int acof = (lane >> 4) * 4;
    const uint32_t aAh = smaddr(&ASh[arow * RS + acof]);
    const uint32_t aAl = smaddr(&ASl[arow * RS + acof]);
    const int nrow = warp_n * 32 + (lane >> 4) * 8 + (lane & 7);
    const int ncof = ((lane >> 3) & 1) * 4;
    const uint32_t aW2h = smaddr(&W2h[nrow * RS + ncof]);
    const uint32_t aW2l = smaddr(&W2l[nrow * RS + ncof]);

    float acc[2][4][4];
#pragma unroll
    for (int a = 0; a < 2; a++)
#pragma unroll
        for (int b = 0; b < 4; b++)
#pragma unroll
            for (int c = 0; c < 4; c++) acc[a][b][c] = 0.f;

    uint4 pvh, pvl;
    float pw2[16];
#define GB_LOAD(K0)                                                        \
    {                                                                      \
        pvh = make_uint4(0, 0, 0, 0); pvl = make_uint4(0, 0, 0, 0);        \
        if (xp >= 0) {                                                     \
            pvh = *(const uint4*)(ash + (K0));                             \
            pvl = *(const uint4*)(asl + (K0));                             \
        }                                                                  \
        const float* p2 = w2p + (size_t)(K0) * HH;                         \
        _Pragma("unroll")                                                  \
        for (int i = 0; i < 16; i++) pw2[i] = p2[i * HH];                  \
    }

    GB_LOAD(0)
    const int NC = DD / 32;
    for (int c = 0; c < NC; c++) {
        const int bo = (c & 1) * STG_U32;
        const uint32_t bob = (uint32_t)(c & 1) * STG_B;
        *(uint4*)&ASh[bo + xrow * RS + xkp] = pvh;
        *(uint4*)&ASl[bo + xrow * RS + xkp] = pvl;
        {
            uint32_t h[8], l[8];
#pragma unroll
            for (int j = 0; j < 8; j++) split_pack(pw2[2 * j], pw2[2 * j + 1], h[j], l[j]);
            *(uint4*)&W2h[bo + hh * RS + qh * 8 + 0] = make_uint4(h[0], h[1], h[2], h[3]);
            *(uint4*)&W2h[bo + hh * RS + qh * 8 + 4] = make_uint4(h[4], h[5], h[6], h[7]);
            *(uint4*)&W2l[bo + hh * RS + qh * 8 + 0] = make_uint4(l[0], l[1], l[2], l[3]);
            *(uint4*)&W2l[bo + hh * RS + qh * 8 + 4] = make_uint4(l[4], l[5], l[6], l[7]);
        }
        if (c + 1 < NC) GB_LOAD((c + 1) * 32)
        __syncthreads();

#pragma unroll
        for (int s = 0; s < 2; s++) {
            const uint32_t s32 = bob + s * 32;
            uint32_t ah[2][4], al[2][4];
            ldm_x4(ah[0], aAh + s32);
            ldm_x4(ah[1], aAh + 16 * RSB + s32);
            ldm_x4(al[0], aAl + s32);
            ldm_x4(al[1], aAl + 16 * RSB + s32);
#pragma unroll
            for (int np = 0; np < 2; np++) {
                uint32_t bh[4], bl[4];
                ldm_x4(bh, aW2h + np * 16 * RSB + s32);
                ldm_x4(bl, aW2l + np * 16 * RSB + s32);
#pragma unroll
                for (int sub = 0; sub < 2; sub++) {
                    int nf = np * 2 + sub;
#pragma unroll
                    for (int mf = 0; mf < 2; mf++) {
                        mma16816(acc[mf][nf], ah[mf], bh + sub * 2);
                        mma16816(acc[mf][nf], ah[mf], bl + sub * 2);
                        mma16816(acc[mf][nf], al[mf], bh + sub * 2);
                    }
                }
            }
        }
    }

#pragma unroll
    for (int mf = 0; mf < 2; mf++) {
        int rbase = warp_m * 32 + mf * 16 + g;
#pragma unroll
        for (int half = 0; half < 2; half++) {
            int r = rbase + half * 8;
            int p = sPair[r];
            if (p < 0) continue;
            int tok = p >> 1;
            float wgt = sW[r];
            float* orow = out + (size_t)tok * HH;
#pragma unroll
            for (int nf = 0; nf < 4; nf++) {
                int hcol = h0 + warp_n * 32 + nf * 8 + q * 2;
                atomicAdd(orow + hcol + 0, acc[mf][nf][half * 2 + 0] * wgt);
                atomicAdd(orow + hcol + 1, acc[mf][nf][half * 2 + 1] * wgt);
            }
        }
    }
}

// ================= fused persistent GEMM kernel =================
__global__ __launch_bounds__(256, 2) void k_fused(const float* __restrict__ w1,
                                                  const float* __restrict__ w3,
                                                  const float* __restrict__ w2,
                                                  float* __restrict__ out) {
    extern __shared__ uint32_t smp[];
    __shared__ int sPair[64];
    __shared__ float sW[64];
    __shared__ int sTask;

    for (;;) {
        __syncthreads();
        if (threadIdx.x == 0) sTask = atomicAdd(&g_task, 1);
        __syncthreads();
        int t = sTask;
        if (t >= NTASK) return;
        if (t < NTASK_A) {
            doA(t >> 3, t & 7, w1, w3, smp, sPair);
        } else {
            t -= NTASK_A;
            doB(t >> 3, t & 7, w2, out, smp, sPair, sW);
        }
    }
}

// ---------------- launch ----------------
extern "C" void kernel_launch(void* const* d_in, const int* in_sizes, int n_in,
                              void* d_out, int out_size) {
    const float* x    = (const float*)d_in[0];
    const float* w1   = (const float*)d_in[1];
    const float* w3   = (const float*)d_in[2];
    const float* w2   = (const float*)d_in[3];
    const float* gate = (const float*)d_in[4];
    float* out = (float*)d_out;
    float* out_lb = (out_size > TT * HH) ? (out + TT * HH) : nullptr;

    cudaFuncSetAttribute(k_fused, cudaFuncAttributeMaxDynamicSharedMemorySize, SMEM_DYN);

    k_routerG<<<dim3(64, 4), 256>>>(x, gate, out);
    k_topk<<<64, 256>>>();
    k_build_tiles2<<<1, 256>>>(out_lb);
    k_fused<<<1024, 256, SMEM_DYN>>>(w1, w3, w2, out);
}